// round 17
// baseline (speedup 1.0000x reference)
#include <cuda_runtime.h>
#include <cuda_fp16.h>
#include <cstdint>

#define NMAX   100000
#define WORDS4 25000          // packed u8x4 degree words
#define RHALF  50000          // nodes per dst-range (2 ranges)
#define SL     74             // slices per range: 2*74 = 148 agg blocks
#define DB     148            // deg blocks

// Scratch (device globals; no allocation allowed)
__device__ float    g_dinv[NMAX];
__device__ __align__(16) __half   g_ph[NMAX];        // p = dinv*x (200KB)
__device__ __align__(16) __half   g_rh[NMAX];        // rho = dinv*(g0-g1) (200KB)
__device__ float    g_rhof[NMAX];                    // rho fp32 for self-loop
__device__ __align__(16) uint32_t g_dpart[DB * WORDS4];  // deg per-block partials
__device__ __align__(16) float    g_part1[SL * NMAX];    // agg1 slice partials
__device__ __align__(16) float    g_part2[SL * NMAX];    // agg2 slice partials

// truly predicated gather: @p LDG, no wavefront when p==0
__device__ __forceinline__ float pred_ldg_half(const __half* addr, int pred) {
    unsigned short r = 0;
    asm volatile("{\n\t"
        ".reg .pred p;\n\t"
        "setp.ne.s32 p, %2, 0;\n\t"
        "@p ld.global.nc.u16 %0, [%1];\n\t"
        "}" : "+h"(r) : "l"(addr), "r"(pred));
    return __half2float(__ushort_as_half(r));
}

// -------- degree: u8x4 smem hist, STG-partial flush --------

__global__ void k_deg(const int* __restrict__ dst, int E) {
    extern __shared__ uint32_t hist[];  // WORDS4 words = 100KB
    for (int i = threadIdx.x; i < WORDS4; i += blockDim.x) hist[i] = 0u;
    __syncthreads();

    int e8 = E >> 3;
    int stride = gridDim.x * blockDim.x;
    for (int i = blockIdx.x * blockDim.x + threadIdx.x; i < e8; i += stride) {
        int4 a = __ldcg(reinterpret_cast<const int4*>(dst) + 2 * i);
        int4 b = __ldcg(reinterpret_cast<const int4*>(dst) + 2 * i + 1);
        atomicAdd(&hist[a.x >> 2], 1u << ((a.x & 3) * 8));
        atomicAdd(&hist[a.y >> 2], 1u << ((a.y & 3) * 8));
        atomicAdd(&hist[a.z >> 2], 1u << ((a.z & 3) * 8));
        atomicAdd(&hist[a.w >> 2], 1u << ((a.w & 3) * 8));
        atomicAdd(&hist[b.x >> 2], 1u << ((b.x & 3) * 8));
        atomicAdd(&hist[b.y >> 2], 1u << ((b.y & 3) * 8));
        atomicAdd(&hist[b.z >> 2], 1u << ((b.z & 3) * 8));
        atomicAdd(&hist[b.w >> 2], 1u << ((b.w & 3) * 8));
    }
    if (blockIdx.x == 0) {  // tail (E % 8)
        for (int e = (e8 << 3) + (int)threadIdx.x; e < E; e += blockDim.x) {
            int d = dst[e];
            atomicAdd(&hist[d >> 2], 1u << ((d & 3) * 8));
        }
    }
    __syncthreads();

    for (int i = threadIdx.x; i < WORDS4; i += blockDim.x)
        g_dpart[blockIdx.x * WORDS4 + i] = hist[i];  // coalesced STG
}

// ---- node1: sum u8x4 partials (4 nodes/thread; byte lanes never carry) ----

__global__ void k_node1(const float* __restrict__ x) {
    int i = blockIdx.x * blockDim.x + threadIdx.x;
    if (i >= WORDS4) return;
    unsigned a0 = 0, a1 = 0, a2 = 0, a3 = 0;
    #pragma unroll
    for (int b = 0; b < DB; b += 4) {  // 148/4 = 37 exact
        a0 += __ldcs(&g_dpart[(b + 0) * WORDS4 + i]);
        a1 += __ldcs(&g_dpart[(b + 1) * WORDS4 + i]);
        a2 += __ldcs(&g_dpart[(b + 2) * WORDS4 + i]);
        a3 += __ldcs(&g_dpart[(b + 3) * WORDS4 + i]);
    }
    unsigned sum = (a0 + a1) + (a2 + a3);  // deg <= ~120 per byte: no carry
    float4 xv = reinterpret_cast<const float4*>(x)[i];
    float d0 = rsqrtf(1.0f + (float)( sum        & 0xFFu));
    float d1 = rsqrtf(1.0f + (float)((sum >>  8) & 0xFFu));
    float d2 = rsqrtf(1.0f + (float)((sum >> 16) & 0xFFu));
    float d3 = rsqrtf(1.0f + (float)( sum >> 24        ));
    reinterpret_cast<float4*>(g_dinv)[i] = make_float4(d0, d1, d2, d3);
    __half2* ph2 = reinterpret_cast<__half2*>(g_ph);
    ph2[2 * i + 0] = __floats2half2_rn(d0 * xv.x, d1 * xv.y);
    ph2[2 * i + 1] = __floats2half2_rn(d2 * xv.z, d3 * xv.w);
}

// ---- agg pass: software-pipelined, truly-predicated gather + smem scatter ----

__device__ __forceinline__ void agg_pass(const int* __restrict__ src,
                                         const int* __restrict__ dst, int E,
                                         const __half* __restrict__ vals,
                                         float* __restrict__ part,
                                         float* tile) {
    int range = blockIdx.x / SL;
    int slice = blockIdx.x % SL;
    int lo = range * RHALF;
    for (int i = threadIdx.x; i < RHALF; i += blockDim.x) tile[i] = 0.0f;
    __syncthreads();

    const int4* src4 = reinterpret_cast<const int4*>(src);
    const int4* dst4 = reinterpret_cast<const int4*>(dst);
    int e8 = E >> 3;
    int step = SL * (int)blockDim.x;
    int i = slice * (int)blockDim.x + (int)threadIdx.x;

    int4 sa, sb, da, db;
    bool have = (i < e8);
    if (have) {
        sa = __ldcg(src4 + 2 * i);     sb = __ldcg(src4 + 2 * i + 1);
        da = __ldcg(dst4 + 2 * i);     db = __ldcg(dst4 + 2 * i + 1);
    }
    while (have) {
        int inext = i + step;
        bool hnext = (inext < e8);
        int4 nsa, nsb, nda, ndb;
        if (hnext) {  // prefetch next iteration's edge words (overlaps gathers)
            nsa = __ldcg(src4 + 2 * inext); nsb = __ldcg(src4 + 2 * inext + 1);
            nda = __ldcg(dst4 + 2 * inext); ndb = __ldcg(dst4 + 2 * inext + 1);
        }
        int t0 = da.x - lo, t1 = da.y - lo, t2 = da.z - lo, t3 = da.w - lo;
        int t4 = db.x - lo, t5 = db.y - lo, t6 = db.z - lo, t7 = db.w - lo;
        int p0 = (unsigned)t0 < RHALF, p1 = (unsigned)t1 < RHALF;
        int p2 = (unsigned)t2 < RHALF, p3 = (unsigned)t3 < RHALF;
        int p4 = (unsigned)t4 < RHALF, p5 = (unsigned)t5 < RHALF;
        int p6 = (unsigned)t6 < RHALF, p7 = (unsigned)t7 < RHALF;
        // 8 batched, truly predicated gathers
        float v0 = pred_ldg_half(&vals[sa.x], p0);
        float v1 = pred_ldg_half(&vals[sa.y], p1);
        float v2 = pred_ldg_half(&vals[sa.z], p2);
        float v3 = pred_ldg_half(&vals[sa.w], p3);
        float v4 = pred_ldg_half(&vals[sb.x], p4);
        float v5 = pred_ldg_half(&vals[sb.y], p5);
        float v6 = pred_ldg_half(&vals[sb.z], p6);
        float v7 = pred_ldg_half(&vals[sb.w], p7);
        if (p0) atomicAdd(&tile[t0], v0);
        if (p1) atomicAdd(&tile[t1], v1);
        if (p2) atomicAdd(&tile[t2], v2);
        if (p3) atomicAdd(&tile[t3], v3);
        if (p4) atomicAdd(&tile[t4], v4);
        if (p5) atomicAdd(&tile[t5], v5);
        if (p6) atomicAdd(&tile[t6], v6);
        if (p7) atomicAdd(&tile[t7], v7);
        i = inext; have = hnext;
        sa = nsa; sb = nsb; da = nda; db = ndb;
    }
    if (slice == 0) {  // tail (E % 8)
        for (int e = (e8 << 3) + (int)threadIdx.x; e < E; e += blockDim.x) {
            int t = dst[e] - lo;
            if ((unsigned)t < RHALF)
                atomicAdd(&tile[t], __half2float(__ldg(&vals[src[e]])));
        }
    }
    __syncthreads();

    for (int i2 = threadIdx.x; i2 < RHALF; i2 += blockDim.x)
        part[slice * NMAX + lo + i2] = tile[i2];  // coalesced STG
}

__global__ void __launch_bounds__(1024, 1)
k_agg1(const int* __restrict__ src, const int* __restrict__ dst, int E) {
    extern __shared__ float tile[];
    agg_pass(src, dst, E, g_ph, g_part1, tile);
}

__global__ void __launch_bounds__(1024, 1)
k_agg2(const int* __restrict__ src, const int* __restrict__ dst, int E) {
    extern __shared__ float tile[];
    agg_pass(src, dst, E, g_rh, g_part2, tile);
}

// ---- node2: 8-acc partial sum + MLP; emit rho ----

__global__ void k_node2(const float* __restrict__ x,
                        const float* __restrict__ W1, const float* __restrict__ b1,
                        const float* __restrict__ W2, int n) {
    int i = blockIdx.x * blockDim.x + threadIdx.x;
    if (i >= n) return;
    float a0 = 0.f, a1 = 0.f, a2 = 0.f, a3 = 0.f;
    float a4 = 0.f, a5 = 0.f, a6 = 0.f, a7 = 0.f;
    #pragma unroll
    for (int s = 0; s < 72; s += 8) {
        a0 += __ldcs(&g_part1[(s + 0) * NMAX + i]);
        a1 += __ldcs(&g_part1[(s + 1) * NMAX + i]);
        a2 += __ldcs(&g_part1[(s + 2) * NMAX + i]);
        a3 += __ldcs(&g_part1[(s + 3) * NMAX + i]);
        a4 += __ldcs(&g_part1[(s + 4) * NMAX + i]);
        a5 += __ldcs(&g_part1[(s + 5) * NMAX + i]);
        a6 += __ldcs(&g_part1[(s + 6) * NMAX + i]);
        a7 += __ldcs(&g_part1[(s + 7) * NMAX + i]);
    }
    a0 += __ldcs(&g_part1[72 * NMAX + i]);
    a1 += __ldcs(&g_part1[73 * NMAX + i]);
    float acc = ((a0 + a1) + (a2 + a3)) + ((a4 + a5) + (a6 + a7));

    float dv = g_dinv[i];
    acc += dv * x[i];          // self-loop term (full precision)
    float sv = dv * acc;       // layer-1 aggregated scalar
    float g0 = 0.0f, g1 = 0.0f;
    #pragma unroll
    for (int j = 0; j < 16; j++) {
        float h = fmaxf(fmaf(sv, __ldg(&W1[j]), __ldg(&b1[j])), 0.0f);
        g0 = fmaf(h, __ldg(&W2[2 * j + 0]), g0);
        g1 = fmaf(h, __ldg(&W2[2 * j + 1]), g1);
    }
    float rho = dv * (g0 - g1);   // scalar layer-2 message (z0-z1 channel)
    g_rh[i] = __float2half(rho);
    g_rhof[i] = rho;
}

// ---- output: 8-acc partial sum; 2-class log_softmax via delta ----

__global__ void k_out(const float* __restrict__ b2, float* __restrict__ out, int n) {
    int i = blockIdx.x * blockDim.x + threadIdx.x;
    if (i >= n) return;
    float db2 = __ldg(&b2[0]) - __ldg(&b2[1]);
    float a0 = 0.f, a1 = 0.f, a2 = 0.f, a3 = 0.f;
    float a4 = 0.f, a5 = 0.f, a6 = 0.f, a7 = 0.f;
    #pragma unroll
    for (int s = 0; s < 72; s += 8) {
        a0 += __ldcs(&g_part2[(s + 0) * NMAX + i]);
        a1 += __ldcs(&g_part2[(s + 1) * NMAX + i]);
        a2 += __ldcs(&g_part2[(s + 2) * NMAX + i]);
        a3 += __ldcs(&g_part2[(s + 3) * NMAX + i]);
        a4 += __ldcs(&g_part2[(s + 4) * NMAX + i]);
        a5 += __ldcs(&g_part2[(s + 5) * NMAX + i]);
        a6 += __ldcs(&g_part2[(s + 6) * NMAX + i]);
        a7 += __ldcs(&g_part2[(s + 7) * NMAX + i]);
    }
    a0 += __ldcs(&g_part2[72 * NMAX + i]);
    a1 += __ldcs(&g_part2[73 * NMAX + i]);
    float acc = ((a0 + a1) + (a2 + a3)) + ((a4 + a5) + (a6 + a7)) + g_rhof[i];

    float delta = fmaf(g_dinv[i], acc, db2);  // z0 - z1
    float l = log1pf(expf(-fabsf(delta)));
    float o0 = (delta >= 0.0f) ? -l : (delta - l);  // z0 - lse
    float o1 = o0 - delta;                          // z1 - lse
    reinterpret_cast<float2*>(out)[i] = make_float2(o0, o1);
}

// ---------------- launch ----------------

extern "C" void kernel_launch(void* const* d_in, const int* in_sizes, int n_in,
                              void* d_out, int out_size) {
    const float* x  = (const float*)d_in[0];
    const int*   ei = (const int*)  d_in[1];
    const float* W1 = (const float*)d_in[2];
    const float* b1 = (const float*)d_in[3];
    const float* W2 = (const float*)d_in[4];
    const float* b2 = (const float*)d_in[5];
    int n = in_sizes[0];        // 100000
    int E = in_sizes[1] / 2;
    const int* src = ei;
    const int* dst = ei + E;

    const int HIST_BYTES = WORDS4 * 4;  // 100 KB
    const int TILE_BYTES = RHALF * 4;   // 200 KB
    cudaFuncSetAttribute(k_deg,  cudaFuncAttributeMaxDynamicSharedMemorySize, HIST_BYTES);
    cudaFuncSetAttribute(k_agg1, cudaFuncAttributeMaxDynamicSharedMemorySize, TILE_BYTES);
    cudaFuncSetAttribute(k_agg2, cudaFuncAttributeMaxDynamicSharedMemorySize, TILE_BYTES);

    const int TB = 256;
    int nb_w = (WORDS4 + TB - 1) / TB;  // 98
    int nb_n = (n + TB - 1) / TB;       // 391

    k_deg  <<<DB, 1024, HIST_BYTES>>>(dst, E);
    k_node1<<<nb_w, TB>>>(x);
    k_agg1 <<<2 * SL, 1024, TILE_BYTES>>>(src, dst, E);
    k_node2<<<nb_n, TB>>>(x, W1, b1, W2, n);
    k_agg2 <<<2 * SL, 1024, TILE_BYTES>>>(src, dst, E);
    k_out  <<<nb_n, TB>>>(b2, (float*)d_out, n);
}